// round 1
// baseline (speedup 1.0000x reference)
#include <cuda_runtime.h>
#include <math.h>

#define D       256
#define TM      64
#define NTHR    512
#define KC      16
#define EPS     1e-5f

typedef unsigned long long u64;

// ---- packed fp32x2 helpers (sm_103a FFMA2 path, only reachable via PTX) ----
__device__ __forceinline__ u64 ffma2(u64 a, u64 b, u64 c) {
    u64 d;
    asm("fma.rn.f32x2 %0, %1, %2, %3;" : "=l"(d) : "l"(a), "l"(b), "l"(c));
    return d;
}
__device__ __forceinline__ u64 packdup(float x) {
    u64 r;
    asm("mov.b64 %0, {%1, %1};" : "=l"(r) : "f"(x));
    return r;
}
__device__ __forceinline__ float2 unpack2(u64 v) {
    float2 f;
    asm("mov.b64 {%0, %1}, %2;" : "=f"(f.x), "=f"(f.y) : "l"(v));
    return f;
}

__device__ __forceinline__ float gelu_exact(float x) {
    return 0.5f * x * (1.0f + erff(x * 0.70710678118654752f));
}

// ---- fused GEMM tile: acc[4][4](f32x2) = As(64xD, smem) @ Wg(DxD, gmem) ----
// Thread (tid): rows trow..trow+3 (trow=(tid>>5)*4), col pairs tcol+64j (tcol=(tid&31)*2)
__device__ __forceinline__ void gemm_tile(const float* __restrict__ As,
                                          const float* __restrict__ Wg,
                                          float* ws, u64 acc[4][4], int tid) {
    const int trow = (tid >> 5) * 4;
    const int tcol = (tid & 31) * 2;
#pragma unroll
    for (int r = 0; r < 4; r++)
#pragma unroll
        for (int j = 0; j < 4; j++) acc[r][j] = 0ULL;

    for (int k0 = 0; k0 < D; k0 += KC) {
        // cooperative load of W chunk rows [k0, k0+KC) -> ws (contiguous, coalesced)
        const float4* src = (const float4*)(Wg + k0 * D);
        float4* dst = (float4*)ws;
        dst[tid]        = src[tid];
        dst[tid + NTHR] = src[tid + NTHR];
        __syncthreads();
#pragma unroll
        for (int kk = 0; kk < KC; kk += 4) {
            float4 a4[4];
#pragma unroll
            for (int r = 0; r < 4; r++)
                a4[r] = *(const float4*)(As + (trow + r) * D + k0 + kk);
#pragma unroll
            for (int u = 0; u < 4; u++) {
                u64 av[4];
#pragma unroll
                for (int r = 0; r < 4; r++)
                    av[r] = packdup(((const float*)&a4[r])[u]);
#pragma unroll
                for (int j = 0; j < 4; j++) {
                    u64 b2 = *(const u64*)(ws + (kk + u) * D + tcol + 64 * j);
#pragma unroll
                    for (int r = 0; r < 4; r++)
                        acc[r][j] = ffma2(av[r], b2, acc[r][j]);
                }
            }
        }
        __syncthreads();
    }
}

// ---- per-row layernorm of a 64xD smem tile ----
__device__ __forceinline__ void layernorm_tile(const float* __restrict__ xs,
                                               float* __restrict__ hs,
                                               const float* __restrict__ g,
                                               const float* __restrict__ be, int tid) {
    const int warp = tid >> 5, lane = tid & 31;
#pragma unroll
    for (int rr = 0; rr < 4; rr++) {
        const int r = warp * 4 + rr;
        const float* row = xs + r * D;
        float s = 0.f, s2 = 0.f;
#pragma unroll
        for (int c = lane; c < D; c += 32) { float v = row[c]; s += v; s2 += v * v; }
#pragma unroll
        for (int o = 16; o; o >>= 1) {
            s  += __shfl_xor_sync(0xFFFFFFFFu, s,  o);
            s2 += __shfl_xor_sync(0xFFFFFFFFu, s2, o);
        }
        const float mu   = s * (1.0f / D);
        const float var  = s2 * (1.0f / D) - mu * mu;
        const float rstd = rsqrtf(var + EPS);
#pragma unroll
        for (int c = lane; c < D; c += 32)
            hs[r * D + c] = (row[c] - mu) * rstd * g[c] + be[c];
    }
}

__global__ __launch_bounds__(NTHR, 1)
void stab_embed_fused(const float* __restrict__ meas, const float* __restrict__ event,
                      const float* __restrict__ leak, const float* __restrict__ event_leak,
                      const int* __restrict__ stab_ids, const int* __restrict__ cycle_ids,
                      const float* __restrict__ w_meas, const float* __restrict__ b_meas,
                      const float* __restrict__ w_event, const float* __restrict__ b_event,
                      const float* __restrict__ w_leak, const float* __restrict__ b_leak,
                      const float* __restrict__ w_el, const float* __restrict__ b_el,
                      const float* __restrict__ stab_table, const float* __restrict__ cycle_table,
                      const float* __restrict__ g1, const float* __restrict__ be1,
                      const float* __restrict__ W11, const float* __restrict__ b11,
                      const float* __restrict__ W12, const float* __restrict__ b12,
                      const float* __restrict__ g2, const float* __restrict__ be2,
                      const float* __restrict__ W21, const float* __restrict__ b21,
                      const float* __restrict__ W22, const float* __restrict__ b22,
                      float* __restrict__ out) {
    extern __shared__ float smem[];
    float* xs = smem;              // 64 x 256  residual stream
    float* hs = smem + TM * D;     // 64 x 256  LN / GELU activations
    float* ws = smem + 2 * TM * D; // KC x 256  streamed weight chunk

    const int tid  = threadIdx.x;
    const int base = blockIdx.x * TM;

    // ---- embed: 4 scalar projections + 2 table gathers -> xs ----
    {
        const int r  = tid >> 3;            // 64 rows
        const int c0 = (tid & 7) * 32;      // 32 cols each
        const int gr = base + r;
        const float m  = meas[gr], e = event[gr], l = leak[gr], el = event_leak[gr];
        const float* srow = stab_table  + (size_t)stab_ids[gr]  * D;
        const float* crow = cycle_table + (size_t)cycle_ids[gr] * D;
#pragma unroll
        for (int c = c0; c < c0 + 32; c++) {
            xs[r * D + c] = m * w_meas[c] + b_meas[c]
                          + e * w_event[c] + b_event[c]
                          + l * w_leak[c] + b_leak[c]
                          + el * w_el[c] + b_el[c]
                          + srow[c] + crow[c];
        }
    }
    __syncthreads();

    const int trow = (tid >> 5) * 4;
    const int tcol = (tid & 31) * 2;
    u64 acc[4][4];

    // ================= residual block 1 =================
    layernorm_tile(xs, hs, g1, be1, tid);
    __syncthreads();

    gemm_tile(hs, W11, ws, acc, tid);           // trailing sync inside covers hs reads
#pragma unroll
    for (int r = 0; r < 4; r++)
#pragma unroll
        for (int j = 0; j < 4; j++) {
            const int col = tcol + 64 * j;
            float2 v = unpack2(acc[r][j]);
            hs[(trow + r) * D + col]     = gelu_exact(v.x + b11[col]);
            hs[(trow + r) * D + col + 1] = gelu_exact(v.y + b11[col + 1]);
        }
    __syncthreads();

    gemm_tile(hs, W12, ws, acc, tid);
#pragma unroll
    for (int r = 0; r < 4; r++)
#pragma unroll
        for (int j = 0; j < 4; j++) {
            const int col = tcol + 64 * j;
            float2 v = unpack2(acc[r][j]);
            xs[(trow + r) * D + col]     += v.x + b12[col];
            xs[(trow + r) * D + col + 1] += v.y + b12[col + 1];
        }
    __syncthreads();

    // ================= residual block 2 =================
    layernorm_tile(xs, hs, g2, be2, tid);
    __syncthreads();

    gemm_tile(hs, W21, ws, acc, tid);
#pragma unroll
    for (int r = 0; r < 4; r++)
#pragma unroll
        for (int j = 0; j < 4; j++) {
            const int col = tcol + 64 * j;
            float2 v = unpack2(acc[r][j]);
            hs[(trow + r) * D + col]     = gelu_exact(v.x + b21[col]);
            hs[(trow + r) * D + col + 1] = gelu_exact(v.y + b21[col + 1]);
        }
    __syncthreads();

    gemm_tile(hs, W22, ws, acc, tid);
#pragma unroll
    for (int r = 0; r < 4; r++)
#pragma unroll
        for (int j = 0; j < 4; j++) {
            const int col = tcol + 64 * j;
            float2 v = unpack2(acc[r][j]);
            const size_t o = (size_t)(base + trow + r) * D + col;
            out[o]     = xs[(trow + r) * D + col]     + v.x + b22[col];
            out[o + 1] = xs[(trow + r) * D + col + 1] + v.y + b22[col + 1];
        }
}

extern "C" void kernel_launch(void* const* d_in, const int* in_sizes, int n_in,
                              void* d_out, int out_size) {
    const float* meas       = (const float*)d_in[0];
    const float* event      = (const float*)d_in[1];
    const float* leak       = (const float*)d_in[2];
    const float* event_leak = (const float*)d_in[3];
    const int*   stab_ids   = (const int*)d_in[4];
    const int*   cycle_ids  = (const int*)d_in[5];
    const float* w_meas  = (const float*)d_in[6];
    const float* b_meas  = (const float*)d_in[7];
    const float* w_event = (const float*)d_in[8];
    const float* b_event = (const float*)d_in[9];
    const float* w_leak  = (const float*)d_in[10];
    const float* b_leak  = (const float*)d_in[11];
    const float* w_el    = (const float*)d_in[12];
    const float* b_el    = (const float*)d_in[13];
    const float* stab_table  = (const float*)d_in[14];
    const float* cycle_table = (const float*)d_in[15];
    const float* g1  = (const float*)d_in[16];
    const float* be1 = (const float*)d_in[17];
    const float* W11 = (const float*)d_in[18];
    const float* b11 = (const float*)d_in[19];
    const float* W12 = (const float*)d_in[20];
    const float* b12 = (const float*)d_in[21];
    const float* g2  = (const float*)d_in[22];
    const float* be2 = (const float*)d_in[23];
    const float* W21 = (const float*)d_in[24];
    const float* b21 = (const float*)d_in[25];
    const float* W22 = (const float*)d_in[26];
    const float* b22 = (const float*)d_in[27];

    const int n_tokens = in_sizes[0];          // B*S = 262144
    const int nblocks  = n_tokens / TM;        // 4096
    const int smem_bytes = (2 * TM * D + KC * D) * (int)sizeof(float);  // 147456

    cudaFuncSetAttribute(stab_embed_fused,
                         cudaFuncAttributeMaxDynamicSharedMemorySize, smem_bytes);

    stab_embed_fused<<<nblocks, NTHR, smem_bytes>>>(
        meas, event, leak, event_leak, stab_ids, cycle_ids,
        w_meas, b_meas, w_event, b_event, w_leak, b_leak, w_el, b_el,
        stab_table, cycle_table,
        g1, be1, W11, b11, W12, b12,
        g2, be2, W21, b21, W22, b22,
        (float*)d_out);
}